// round 1
// baseline (speedup 1.0000x reference)
#include <cuda_runtime.h>
#include <cstring>

// Problem constants (fixed shapes for this problem)
#define A_ANG 8
#define F 64                    // in_size == out_size == 64
#define MAX_N 20000
#define MAX_M (A_ANG * MAX_N)   // 160000
#define CAP 64                  // bucket capacity per row (Poisson(16) -> overflow prob ~1e-12/row)

// ---------------- scratch (device globals: allocation-free per harness rules) ---------
__device__ int   g_cnt[MAX_M];                          // per-row edge counts
__device__ uint2 g_edges[(size_t)MAX_M * CAP];          // {col, val-bits} buckets, 82MB
__device__ float g_tx[3ull * MAX_M * F];                // three ping-pong feature buffers, 123MB

// ---------------- helpers ----------------
__device__ __forceinline__ float2 ffma2(float2 a, float2 b, float2 c) {
    unsigned long long ua, ub, uc, ud;
    memcpy(&ua, &a, 8); memcpy(&ub, &b, 8); memcpy(&uc, &c, 8);
    asm("fma.rn.f32x2 %0, %1, %2, %3;" : "=l"(ud) : "l"(ua), "l"(ub), "l"(uc));
    float2 d; memcpy(&d, &ud, 8);
    return d;
}

// ---------------- kernels ----------------
__global__ void zero_cnt_kernel(int M) {
    int i = blockIdx.x * blockDim.x + threadIdx.x;
    if (i < M) g_cnt[i] = 0;
}

__global__ void build_buckets_kernel(const int* __restrict__ rows,
                                     const int* __restrict__ cols,
                                     const float* __restrict__ vals, int E) {
    int e = blockIdx.x * blockDim.x + threadIdx.x;
    if (e >= E) return;
    int r = rows[e];
    int p = atomicAdd(&g_cnt[r], 1);
    if (p < CAP)
        g_edges[(size_t)r * CAP + p] = make_uint2((unsigned)cols[e], __float_as_uint(vals[e]));
}

// Tx0[a*N + n][:] = x[n][:]
__global__ void tile_x_kernel(const float* __restrict__ x, float* __restrict__ tx0, int N) {
    int idx = blockIdx.x * blockDim.x + threadIdx.x;   // over M * (F/4) float4s
    int total = A_ANG * N * (F / 4);
    if (idx >= total) return;
    int c4 = idx & 15;
    int m  = idx >> 4;
    int n  = m % N;
    ((float4*)tx0)[idx] = __ldg((const float4*)x + n * (F / 4) + c4);
}

// One warp per row. dst = spmm(src)           (first=1)
//                   dst = 2*spmm(src) - prev  (first=0)
__global__ void spmm_cheb_kernel(const float* __restrict__ src,
                                 const float* __restrict__ prev,
                                 float* __restrict__ dst, int M, int first) {
    int w = (int)((blockIdx.x * blockDim.x + threadIdx.x) >> 5);
    if (w >= M) return;
    int lane = threadIdx.x & 31;

    int cnt = g_cnt[w];
    if (cnt > CAP) cnt = CAP;
    const uint2* ep = g_edges + (size_t)w * CAP;

    float ax0 = 0.f, ay0 = 0.f, ax1 = 0.f, ay1 = 0.f;
    int i = 0;
    for (; i + 1 < cnt; i += 2) {
        uint2 e0 = __ldg(&ep[i]);
        uint2 e1 = __ldg(&ep[i + 1]);
        float2 t0 = __ldg((const float2*)(src + (size_t)e0.x * F) + lane);
        float2 t1 = __ldg((const float2*)(src + (size_t)e1.x * F) + lane);
        float v0 = __uint_as_float(e0.y);
        float v1 = __uint_as_float(e1.y);
        ax0 += v0 * t0.x; ay0 += v0 * t0.y;
        ax1 += v1 * t1.x; ay1 += v1 * t1.y;
    }
    if (i < cnt) {
        uint2 e0 = __ldg(&ep[i]);
        float2 t0 = __ldg((const float2*)(src + (size_t)e0.x * F) + lane);
        float v0 = __uint_as_float(e0.y);
        ax0 += v0 * t0.x; ay0 += v0 * t0.y;
    }
    float sx = ax0 + ax1, sy = ay0 + ay1;

    float2 o;
    if (first) {
        o.x = sx; o.y = sy;
    } else {
        float2 p = __ldg((const float2*)(prev + (size_t)w * F) + lane);
        o.x = 2.f * sx - p.x;
        o.y = 2.f * sy - p.y;
    }
    ((float2*)(dst + (size_t)w * F))[lane] = o;
}

// out[n][o] (+)= sum_a sum_i src[a*N+n][i] * Wk[a*64+i][o]   (+ bias if init)
// Block: 64 nodes x 64 outs, 256 threads. Thread: 2 nodes x 8 outs (4 float2), FFMA2.
__global__ __launch_bounds__(256) void gemm_acc_kernel(const float* __restrict__ src,
                                                       const float* __restrict__ Wk,
                                                       const float* __restrict__ bias,
                                                       float* __restrict__ out,
                                                       int N, int initOut) {
    __shared__ float Sv[64][68];   // 64 nodes x 64 feats (pad 68: float4-aligned rows, conflict-free)
    __shared__ float Sw[64][68];   // 64 j x 64 outs

    int tid = threadIdx.x;
    int nodeBase = blockIdx.x * 64;
    int ty = tid >> 3;      // 0..31
    int tx = tid & 7;       // 0..7
    int n0 = 2 * ty, n1 = 2 * ty + 1;

    float2 acc0[4], acc1[4];
#pragma unroll
    for (int i = 0; i < 4; i++) {
        acc0[i] = make_float2(0.f, 0.f);
        acc1[i] = make_float2(0.f, 0.f);
    }

    for (int a = 0; a < A_ANG; a++) {
        // stage feature tile
#pragma unroll 2
        for (int i = tid; i < 64 * 16; i += 256) {
            int r = i >> 4, c4 = i & 15;
            int n = nodeBase + r;
            float4 v = make_float4(0.f, 0.f, 0.f, 0.f);
            if (n < N) v = __ldg((const float4*)(src + ((size_t)a * N + n) * F) + c4);
            *(float4*)&Sv[r][c4 * 4] = v;
        }
        // stage weight tile
#pragma unroll 2
        for (int i = tid; i < 64 * 16; i += 256) {
            int r = i >> 4, c4 = i & 15;
            float4 v = __ldg((const float4*)(Wk + (size_t)(a * F + r) * F) + c4);
            *(float4*)&Sw[r][c4 * 4] = v;
        }
        __syncthreads();

#pragma unroll 8
        for (int jj = 0; jj < 64; jj++) {
            float v0 = Sv[n0][jj];
            float v1 = Sv[n1][jj];
            float2 vv0 = make_float2(v0, v0);
            float2 vv1 = make_float2(v1, v1);
#pragma unroll
            for (int i = 0; i < 4; i++) {
                float2 w = *(const float2*)&Sw[jj][tx * 8 + 2 * i];
                acc0[i] = ffma2(vv0, w, acc0[i]);
                acc1[i] = ffma2(vv1, w, acc1[i]);
            }
        }
        __syncthreads();
    }

    int gn0 = nodeBase + n0;
    int gn1 = nodeBase + n1;
#pragma unroll
    for (int i = 0; i < 4; i++) {
        int o = tx * 8 + 2 * i;
        float2 b2 = *(const float2*)(bias + o);
        if (gn0 < N) {
            float2* p = (float2*)(out + (size_t)gn0 * F + o);
            float2 r = acc0[i];
            if (initOut) { r.x += b2.x; r.y += b2.y; }
            else { float2 old = *p; r.x += old.x; r.y += old.y; }
            *p = r;
        }
        if (gn1 < N) {
            float2* p = (float2*)(out + (size_t)gn1 * F + o);
            float2 r = acc1[i];
            if (initOut) { r.x += b2.x; r.y += b2.y; }
            else { float2 old = *p; r.x += old.x; r.y += old.y; }
            *p = r;
        }
    }
}

// ---------------- launch ----------------
extern "C" void kernel_launch(void* const* d_in, const int* in_sizes, int n_in,
                              void* d_out, int out_size) {
    const float* x       = (const float*)d_in[0];
    const float* ls_vals = (const float*)d_in[1];
    const float* weight  = (const float*)d_in[2];
    const float* bias    = (const float*)d_in[3];
    const int*   ls_rows = (const int*)d_in[4];
    const int*   ls_cols = (const int*)d_in[5];

    int N = in_sizes[0] / F;
    int E = in_sizes[1];
    int M = A_ANG * N;
    int K = in_sizes[2] / (A_ANG * F * F);
    float* out = (float*)d_out;

    float* txbuf;
    {
        void* p = nullptr;
        cudaGetSymbolAddress(&p, g_tx);
        txbuf = (float*)p;
    }
    float* tx[3] = { txbuf,
                     txbuf + (size_t)MAX_M * F,
                     txbuf + 2ull * MAX_M * F };

    const int spmm_blocks = (M + 7) / 8;       // 8 warps (rows) per 256-thread block
    const int gemm_blocks = (N + 63) / 64;

    // 1. build per-row edge buckets (one-pass counting "sort")
    zero_cnt_kernel<<<(M + 255) / 256, 256>>>(M);
    build_buckets_kernel<<<(E + 255) / 256, 256>>>(ls_rows, ls_cols, ls_vals, E);

    // 2. Tx0 = tile(x)
    tile_x_kernel<<<(M * (F / 4) + 255) / 256, 256>>>(x, tx[0], N);

    // 3. out = feat(Tx0) @ W0 + bias
    gemm_acc_kernel<<<gemm_blocks, 256>>>(tx[0], weight, bias, out, N, 1);

    // 4. Tx1 = L @ Tx0 ; out += feat(Tx1) @ W1
    spmm_cheb_kernel<<<spmm_blocks, 256>>>(tx[0], nullptr, tx[1], M, 1);
    gemm_acc_kernel<<<gemm_blocks, 256>>>(tx[1], weight + (size_t)1 * A_ANG * F * F,
                                          bias, out, N, 0);

    // 5. Chebyshev recurrence
    int ia = 0, ib = 1, ic = 2;
    for (int k = 2; k < K; k++) {
        spmm_cheb_kernel<<<spmm_blocks, 256>>>(tx[ib], tx[ia], tx[ic], M, 0);
        gemm_acc_kernel<<<gemm_blocks, 256>>>(tx[ic], weight + (size_t)k * A_ANG * F * F,
                                              bias, out, N, 0);
        int t = ia; ia = ib; ib = ic; ic = t;
    }
}

// round 3
// speedup vs baseline: 1.4334x; 1.4334x over previous
#include <cuda_runtime.h>
#include <cstring>

// Problem constants (fixed shapes for this problem)
#define A_ANG 8
#define F 64                    // in_size == out_size == 64
#define MAX_N 20000
#define MAX_M (A_ANG * MAX_N)   // 160000
#define CAP 64                  // bucket capacity per row (Poisson(16) -> overflow prob ~1e-12/row)

// ---------------- scratch (device globals: allocation-free per harness rules) ---------
__device__ int   g_cnt[MAX_M];                          // per-row edge counts
__device__ uint2 g_edges[(size_t)MAX_M * CAP];          // {col, val-bits} buckets, 82MB
__device__ float g_tx[3ull * MAX_M * F];                // three ping-pong feature buffers, 123MB

// ---------------- helpers ----------------
__device__ __forceinline__ float2 ffma2(float2 a, float2 b, float2 c) {
    unsigned long long ua, ub, uc, ud;
    memcpy(&ua, &a, 8); memcpy(&ub, &b, 8); memcpy(&uc, &c, 8);
    asm("fma.rn.f32x2 %0, %1, %2, %3;" : "=l"(ud) : "l"(ua), "l"(ub), "l"(uc));
    float2 d; memcpy(&d, &ud, 8);
    return d;
}

// ---------------- kernels ----------------
__global__ void zero_cnt_kernel(int M) {
    int i = blockIdx.x * blockDim.x + threadIdx.x;
    if (i < M) g_cnt[i] = 0;
}

__global__ void build_buckets_kernel(const int* __restrict__ rows,
                                     const int* __restrict__ cols,
                                     const float* __restrict__ vals, int E) {
    int e = blockIdx.x * blockDim.x + threadIdx.x;
    if (e >= E) return;
    int r = rows[e];
    int p = atomicAdd(&g_cnt[r], 1);
    if (p < CAP)
        g_edges[(size_t)r * CAP + p] = make_uint2((unsigned)cols[e], __float_as_uint(vals[e]));
}

// Tx0[a*N + n][:] = x[n][:]
__global__ void tile_x_kernel(const float* __restrict__ x, float* __restrict__ tx0, int N) {
    int idx = blockIdx.x * blockDim.x + threadIdx.x;   // over M * (F/4) float4s
    int total = A_ANG * N * (F / 4);
    if (idx >= total) return;
    int c4 = idx & 15;
    int m  = idx >> 4;
    int n  = m % N;
    ((float4*)tx0)[idx] = __ldg((const float4*)x + n * (F / 4) + c4);
}

// One warp per row. dst = spmm(src)           (first=1)
//                   dst = 2*spmm(src) - prev  (first=0)
__global__ void spmm_cheb_kernel(const float* __restrict__ src,
                                 const float* __restrict__ prev,
                                 float* __restrict__ dst, int M, int first) {
    int w = (int)((blockIdx.x * blockDim.x + threadIdx.x) >> 5);
    if (w >= M) return;
    int lane = threadIdx.x & 31;

    int cnt = g_cnt[w];
    if (cnt > CAP) cnt = CAP;
    const uint2* ep = g_edges + (size_t)w * CAP;

    float ax0 = 0.f, ay0 = 0.f, ax1 = 0.f, ay1 = 0.f;
    float ax2 = 0.f, ay2 = 0.f, ax3 = 0.f, ay3 = 0.f;
    int i = 0;
    // 4-wide unroll: uint4 loads pull 2 edges each; 4 gathers in flight per warp
    for (; i + 3 < cnt; i += 4) {
        uint4 e01 = __ldg((const uint4*)(ep + i));
        uint4 e23 = __ldg((const uint4*)(ep + i + 2));
        float2 t0 = __ldg((const float2*)(src + (size_t)e01.x * F) + lane);
        float2 t1 = __ldg((const float2*)(src + (size_t)e01.z * F) + lane);
        float2 t2 = __ldg((const float2*)(src + (size_t)e23.x * F) + lane);
        float2 t3 = __ldg((const float2*)(src + (size_t)e23.z * F) + lane);
        float v0 = __uint_as_float(e01.y);
        float v1 = __uint_as_float(e01.w);
        float v2 = __uint_as_float(e23.y);
        float v3 = __uint_as_float(e23.w);
        ax0 += v0 * t0.x; ay0 += v0 * t0.y;
        ax1 += v1 * t1.x; ay1 += v1 * t1.y;
        ax2 += v2 * t2.x; ay2 += v2 * t2.y;
        ax3 += v3 * t3.x; ay3 += v3 * t3.y;
    }
    for (; i < cnt; i++) {
        uint2 e0 = __ldg(&ep[i]);
        float2 t0 = __ldg((const float2*)(src + (size_t)e0.x * F) + lane);
        float v0 = __uint_as_float(e0.y);
        ax0 += v0 * t0.x; ay0 += v0 * t0.y;
    }
    float sx = (ax0 + ax1) + (ax2 + ax3);
    float sy = (ay0 + ay1) + (ay2 + ay3);

    float2 o;
    if (first) {
        o.x = sx; o.y = sy;
    } else {
        float2 p = __ldg((const float2*)(prev + (size_t)w * F) + lane);
        o.x = 2.f * sx - p.x;
        o.y = 2.f * sy - p.y;
    }
    ((float2*)(dst + (size_t)w * F))[lane] = o;
}

// out[n][o] (+)= sum_a sum_i src[a*N+n][i] * Wk[a*64+i][o]   (+ bias if init)
// Block: 64 nodes x 64 outs, 256 threads. Thread: 2 nodes x 8 outs.
// Feature tile staged TRANSPOSED (Svt[j][node]) so the 2 node values are one LDS.64.
// Per jj per thread: 1 LDS.64 + 2 LDS.128 -> 8 FFMA2. FMA-pipe bound by design.
__global__ __launch_bounds__(256) void gemm_acc_kernel(const float* __restrict__ src,
                                                       const float* __restrict__ Wk,
                                                       const float* __restrict__ bias,
                                                       float* __restrict__ out,
                                                       int N, int initOut) {
    __shared__ float Svt[64][66];  // [j][node]; pad 66: 264B rows keep 8B align, 4-way-max store conflicts
    __shared__ float Sw[64][68];   // [j][out];  pad 68: 272B rows keep 16B align

    int tid = threadIdx.x;
    int nodeBase = blockIdx.x * 64;
    int ty = tid >> 3;      // 0..31 -> node pair
    int tx = tid & 7;       // 0..7  -> out group of 8
    int n0 = 2 * ty, n1 = 2 * ty + 1;

    float2 acc0[4], acc1[4];
#pragma unroll
    for (int i = 0; i < 4; i++) {
        acc0[i] = make_float2(0.f, 0.f);
        acc1[i] = make_float2(0.f, 0.f);
    }

    for (int a = 0; a < A_ANG; a++) {
        // stage feature tile (transposed into Svt[j][node])
#pragma unroll
        for (int i = tid; i < 64 * 16; i += 256) {
            int r = i >> 4, c4 = i & 15;
            int n = nodeBase + r;
            float4 v = make_float4(0.f, 0.f, 0.f, 0.f);
            if (n < N) v = __ldg((const float4*)(src + ((size_t)a * N + n) * F) + c4);
            Svt[4 * c4 + 0][r] = v.x;
            Svt[4 * c4 + 1][r] = v.y;
            Svt[4 * c4 + 2][r] = v.z;
            Svt[4 * c4 + 3][r] = v.w;
        }
        // stage weight tile
#pragma unroll
        for (int i = tid; i < 64 * 16; i += 256) {
            int r = i >> 4, c4 = i & 15;
            float4 v = __ldg((const float4*)(Wk + (size_t)(a * F + r) * F) + c4);
            *(float4*)&Sw[r][c4 * 4] = v;
        }
        __syncthreads();

#pragma unroll 8
        for (int jj = 0; jj < 64; jj++) {
            float2 v  = *(const float2*)&Svt[jj][n0];
            float4 w0 = *(const float4*)&Sw[jj][tx * 8];
            float4 w1 = *(const float4*)&Sw[jj][tx * 8 + 4];
            float2 vv0 = make_float2(v.x, v.x);
            float2 vv1 = make_float2(v.y, v.y);
            acc0[0] = ffma2(vv0, make_float2(w0.x, w0.y), acc0[0]);
            acc0[1] = ffma2(vv0, make_float2(w0.z, w0.w), acc0[1]);
            acc0[2] = ffma2(vv0, make_float2(w1.x, w1.y), acc0[2]);
            acc0[3] = ffma2(vv0, make_float2(w1.z, w1.w), acc0[3]);
            acc1[0] = ffma2(vv1, make_float2(w0.x, w0.y), acc1[0]);
            acc1[1] = ffma2(vv1, make_float2(w0.z, w0.w), acc1[1]);
            acc1[2] = ffma2(vv1, make_float2(w1.x, w1.y), acc1[2]);
            acc1[3] = ffma2(vv1, make_float2(w1.z, w1.w), acc1[3]);
        }
        __syncthreads();
    }

    int gn0 = nodeBase + n0;
    int gn1 = nodeBase + n1;
#pragma unroll
    for (int i = 0; i < 4; i++) {
        int o = tx * 8 + 2 * i;
        float2 b2 = *(const float2*)(bias + o);
        if (gn0 < N) {
            float2* p = (float2*)(out + (size_t)gn0 * F + o);
            float2 r = acc0[i];
            if (initOut) { r.x += b2.x; r.y += b2.y; }
            else { float2 old = *p; r.x += old.x; r.y += old.y; }
            *p = r;
        }
        if (gn1 < N) {
            float2* p = (float2*)(out + (size_t)gn1 * F + o);
            float2 r = acc1[i];
            if (initOut) { r.x += b2.x; r.y += b2.y; }
            else { float2 old = *p; r.x += old.x; r.y += old.y; }
            *p = r;
        }
    }
}

// ---------------- launch ----------------
extern "C" void kernel_launch(void* const* d_in, const int* in_sizes, int n_in,
                              void* d_out, int out_size) {
    const float* x       = (const float*)d_in[0];
    const float* ls_vals = (const float*)d_in[1];
    const float* weight  = (const float*)d_in[2];
    const float* bias    = (const float*)d_in[3];
    const int*   ls_rows = (const int*)d_in[4];
    const int*   ls_cols = (const int*)d_in[5];

    int N = in_sizes[0] / F;
    int E = in_sizes[1];
    int M = A_ANG * N;
    int K = in_sizes[2] / (A_ANG * F * F);
    float* out = (float*)d_out;

    float* txbuf;
    {
        void* p = nullptr;
        cudaGetSymbolAddress(&p, g_tx);
        txbuf = (float*)p;
    }
    float* tx[3] = { txbuf,
                     txbuf + (size_t)MAX_M * F,
                     txbuf + 2ull * MAX_M * F };

    const int spmm_blocks = (M + 7) / 8;       // 8 warps (rows) per 256-thread block
    const int gemm_blocks = (N + 63) / 64;

    // 1. build per-row edge buckets (one-pass counting "sort")
    zero_cnt_kernel<<<(M + 255) / 256, 256>>>(M);
    build_buckets_kernel<<<(E + 255) / 256, 256>>>(ls_rows, ls_cols, ls_vals, E);

    // 2. Tx0 = tile(x)
    tile_x_kernel<<<(M * (F / 4) + 255) / 256, 256>>>(x, tx[0], N);

    // 3. out = feat(Tx0) @ W0 + bias
    gemm_acc_kernel<<<gemm_blocks, 256>>>(tx[0], weight, bias, out, N, 1);

    // 4. Tx1 = L @ Tx0 ; out += feat(Tx1) @ W1
    spmm_cheb_kernel<<<spmm_blocks, 256>>>(tx[0], nullptr, tx[1], M, 1);
    gemm_acc_kernel<<<gemm_blocks, 256>>>(tx[1], weight + (size_t)1 * A_ANG * F * F,
                                          bias, out, N, 0);

    // 5. Chebyshev recurrence
    int ia = 0, ib = 1, ic = 2;
    for (int k = 2; k < K; k++) {
        spmm_cheb_kernel<<<spmm_blocks, 256>>>(tx[ib], tx[ia], tx[ic], M, 0);
        gemm_acc_kernel<<<gemm_blocks, 256>>>(tx[ic], weight + (size_t)k * A_ANG * F * F,
                                              bias, out, N, 0);
        int t = ia; ia = ib; ib = ic; ic = t;
    }
}

// round 7
// speedup vs baseline: 2.1015x; 1.4661x over previous
#include <cuda_runtime.h>
#include <cstring>

// Problem constants (fixed shapes for this problem)
#define A_ANG 8
#define F 64                    // in_size == out_size == 64
#define MAX_N 20000
#define MAX_M (A_ANG * MAX_N)   // 160000
#define CAP 64                  // bucket capacity per row (Poisson(16) -> overflow prob ~1e-12/row)

// ---------------- scratch (device globals: allocation-free per harness rules) ---------
__device__ int   g_cnt[MAX_M];                          // per-row edge counts
__device__ uint2 g_edges[(size_t)MAX_M * CAP];          // {col, val-bits} buckets, 82MB
__device__ float g_tx[3ull * MAX_M * F];                // three ping-pong feature buffers, 123MB

// ---------------- helpers ----------------
__device__ __forceinline__ float2 ffma2(float2 a, float2 b, float2 c) {
    unsigned long long ua, ub, uc, ud;
    memcpy(&ua, &a, 8); memcpy(&ub, &b, 8); memcpy(&uc, &c, 8);
    asm("fma.rn.f32x2 %0, %1, %2, %3;" : "=l"(ud) : "l"(ua), "l"(ub), "l"(uc));
    float2 d; memcpy(&d, &ud, 8);
    return d;
}

// ---------------- kernels ----------------
__global__ void zero_cnt_kernel(int M) {
    int i = blockIdx.x * blockDim.x + threadIdx.x;
    if (i < M) g_cnt[i] = 0;
}

__global__ void build_buckets_kernel(const int* __restrict__ rows,
                                     const int* __restrict__ cols,
                                     const float* __restrict__ vals, int E) {
    int e = blockIdx.x * blockDim.x + threadIdx.x;
    if (e >= E) return;
    int r = rows[e];
    int p = atomicAdd(&g_cnt[r], 1);
    if (p < CAP)
        g_edges[(size_t)r * CAP + p] = make_uint2((unsigned)cols[e], __float_as_uint(vals[e]));
}

// Tx0[a*N + n][:] = x[n][:]
__global__ void tile_x_kernel(const float* __restrict__ x, float* __restrict__ tx0, int N) {
    int idx = blockIdx.x * blockDim.x + threadIdx.x;   // over M * (F/4) float4s
    int total = A_ANG * N * (F / 4);
    if (idx >= total) return;
    int c4 = idx & 15;
    int m  = idx >> 4;
    int n  = m % N;
    ((float4*)tx0)[idx] = __ldg((const float4*)x + n * (F / 4) + c4);
}

// One warp per row. dst = spmm(src)           (first=1)
//                   dst = 2*spmm(src) - prev  (first=0)
__global__ void spmm_cheb_kernel(const float* __restrict__ src,
                                 const float* __restrict__ prev,
                                 float* __restrict__ dst, int M, int first) {
    int w = (int)((blockIdx.x * blockDim.x + threadIdx.x) >> 5);
    if (w >= M) return;
    int lane = threadIdx.x & 31;

    int cnt = g_cnt[w];
    if (cnt > CAP) cnt = CAP;
    const uint2* ep = g_edges + (size_t)w * CAP;

    float ax0 = 0.f, ay0 = 0.f, ax1 = 0.f, ay1 = 0.f;
    float ax2 = 0.f, ay2 = 0.f, ax3 = 0.f, ay3 = 0.f;
    int i = 0;
    // 4-wide unroll: uint4 loads pull 2 edges each; 4 gathers in flight per warp
    for (; i + 3 < cnt; i += 4) {
        uint4 e01 = __ldg((const uint4*)(ep + i));
        uint4 e23 = __ldg((const uint4*)(ep + i + 2));
        float2 t0 = __ldg((const float2*)(src + (size_t)e01.x * F) + lane);
        float2 t1 = __ldg((const float2*)(src + (size_t)e01.z * F) + lane);
        float2 t2 = __ldg((const float2*)(src + (size_t)e23.x * F) + lane);
        float2 t3 = __ldg((const float2*)(src + (size_t)e23.z * F) + lane);
        float v0 = __uint_as_float(e01.y);
        float v1 = __uint_as_float(e01.w);
        float v2 = __uint_as_float(e23.y);
        float v3 = __uint_as_float(e23.w);
        ax0 += v0 * t0.x; ay0 += v0 * t0.y;
        ax1 += v1 * t1.x; ay1 += v1 * t1.y;
        ax2 += v2 * t2.x; ay2 += v2 * t2.y;
        ax3 += v3 * t3.x; ay3 += v3 * t3.y;
    }
    for (; i < cnt; i++) {
        uint2 e0 = __ldg(&ep[i]);
        float2 t0 = __ldg((const float2*)(src + (size_t)e0.x * F) + lane);
        float v0 = __uint_as_float(e0.y);
        ax0 += v0 * t0.x; ay0 += v0 * t0.y;
    }
    float sx = (ax0 + ax1) + (ax2 + ax3);
    float sy = (ay0 + ay1) + (ay2 + ay3);

    float2 o;
    if (first) {
        o.x = sx; o.y = sy;
    } else {
        float2 p = __ldg((const float2*)(prev + (size_t)w * F) + lane);
        o.x = 2.f * sx - p.x;
        o.y = 2.f * sy - p.y;
    }
    ((float2*)(dst + (size_t)w * F))[lane] = o;
}

// out[n][o] (+)= sum_a sum_i src[a*N+n][i] * Wk[a*64+i][o]   (+ bias if init)
// Block: 128 threads = 4 warps; tile 64 nodes x 64 outs.
// Warp (r,c) owns a 32-node x 32-out quadrant. Lane: ln=l&7 -> 4 nodes, lo=l>>3 -> 8 outs.
// Weight LDS are warp-broadcast (4 distinct addrs/warp -> ~free on crossbar);
// node LDS are scalar, pad-65 rows: bank = (node + jj) mod 32, 8 distinct nodes
// spaced 4 -> 8 distinct banks, 4-way broadcast -> conflict-free.
// Sv staged with SCALAR stores (pad-65 rows are only 4B-aligned; STS.128 would trap).
__global__ __launch_bounds__(128) void gemm_acc_kernel(const float* __restrict__ src,
                                                       const float* __restrict__ Wk,
                                                       const float* __restrict__ bias,
                                                       float* __restrict__ out,
                                                       int N, int initOut) {
    __shared__ float Sv[64][65];   // [node][j]; pad 65 -> conflict-free scalar column reads
    __shared__ float Sw[64][68];   // [j][out];  pad 68: 272B rows keep 16B align

    int tid = threadIdx.x;
    int lane = tid & 31;
    int w = tid >> 5;            // 0..3
    int r = w & 1;               // node half
    int c = w >> 1;              // out half
    int ln = lane & 7;           // node group of 4 within half
    int lo = lane >> 3;          // out group of 8 within half
    int nodeBase = blockIdx.x * 64;
    int nLoc = 32 * r + 4 * ln;  // local node base (4 nodes)
    int oLoc = 32 * c + 8 * lo;  // local out base (8 outs)

    float2 acc[4][4];
#pragma unroll
    for (int q = 0; q < 4; q++)
#pragma unroll
        for (int i = 0; i < 4; i++) acc[q][i] = make_float2(0.f, 0.f);

    for (int a = 0; a < A_ANG; a++) {
        // stage feature tile (natural layout Sv[node][j]); scalar STS (alignment-safe)
#pragma unroll
        for (int i = tid; i < 64 * 16; i += 128) {
            int rr = i >> 4, c4 = i & 15;
            int n = nodeBase + rr;
            float4 v = make_float4(0.f, 0.f, 0.f, 0.f);
            if (n < N) v = __ldg((const float4*)(src + ((size_t)a * N + n) * F) + c4);
            Sv[rr][c4 * 4 + 0] = v.x;
            Sv[rr][c4 * 4 + 1] = v.y;
            Sv[rr][c4 * 4 + 2] = v.z;
            Sv[rr][c4 * 4 + 3] = v.w;
        }
        // stage weight tile (rows 272B -> 16B aligned, STS.128 OK)
#pragma unroll
        for (int i = tid; i < 64 * 16; i += 128) {
            int rr = i >> 4, c4 = i & 15;
            float4 v = __ldg((const float4*)(Wk + (size_t)(a * F + rr) * F) + c4);
            *(float4*)&Sw[rr][c4 * 4] = v;
        }
        __syncthreads();

#pragma unroll 4
        for (int jj = 0; jj < 64; jj++) {
            // 4 node values (scalar LDS, conflict-free via pad-65)
            float v0 = Sv[nLoc + 0][jj];
            float v1 = Sv[nLoc + 1][jj];
            float v2 = Sv[nLoc + 2][jj];
            float v3 = Sv[nLoc + 3][jj];
            // 8 weights, warp-broadcast (only 4 distinct addresses per warp)
            float4 w0 = *(const float4*)&Sw[jj][oLoc];
            float4 w1 = *(const float4*)&Sw[jj][oLoc + 4];
            float2 wp[4] = { make_float2(w0.x, w0.y), make_float2(w0.z, w0.w),
                             make_float2(w1.x, w1.y), make_float2(w1.z, w1.w) };
            float2 vv0 = make_float2(v0, v0);
            float2 vv1 = make_float2(v1, v1);
            float2 vv2 = make_float2(v2, v2);
            float2 vv3 = make_float2(v3, v3);
#pragma unroll
            for (int i = 0; i < 4; i++) {
                acc[0][i] = ffma2(vv0, wp[i], acc[0][i]);
                acc[1][i] = ffma2(vv1, wp[i], acc[1][i]);
                acc[2][i] = ffma2(vv2, wp[i], acc[2][i]);
                acc[3][i] = ffma2(vv3, wp[i], acc[3][i]);
            }
        }
        __syncthreads();
    }

    // epilogue: 4 nodes x 8 outs per thread
#pragma unroll
    for (int q = 0; q < 4; q++) {
        int gn = nodeBase + nLoc + q;
        if (gn >= N) continue;
#pragma unroll
        for (int i = 0; i < 4; i++) {
            int o = oLoc + 2 * i;
            float2* p = (float2*)(out + (size_t)gn * F + o);
            float2 res = acc[q][i];
            if (initOut) {
                float2 b2 = *(const float2*)(bias + o);
                res.x += b2.x; res.y += b2.y;
            } else {
                float2 old = *p;
                res.x += old.x; res.y += old.y;
            }
            *p = res;
        }
    }
}

// ---------------- launch ----------------
extern "C" void kernel_launch(void* const* d_in, const int* in_sizes, int n_in,
                              void* d_out, int out_size) {
    const float* x       = (const float*)d_in[0];
    const float* ls_vals = (const float*)d_in[1];
    const float* weight  = (const float*)d_in[2];
    const float* bias    = (const float*)d_in[3];
    const int*   ls_rows = (const int*)d_in[4];
    const int*   ls_cols = (const int*)d_in[5];

    int N = in_sizes[0] / F;
    int E = in_sizes[1];
    int M = A_ANG * N;
    int K = in_sizes[2] / (A_ANG * F * F);
    float* out = (float*)d_out;

    float* txbuf;
    {
        void* p = nullptr;
        cudaGetSymbolAddress(&p, g_tx);
        txbuf = (float*)p;
    }
    float* tx[3] = { txbuf,
                     txbuf + (size_t)MAX_M * F,
                     txbuf + 2ull * MAX_M * F };

    const int spmm_blocks = (M + 7) / 8;       // 8 warps (rows) per 256-thread block
    const int gemm_blocks = (N + 63) / 64;

    // 1. build per-row edge buckets (one-pass counting "sort")
    zero_cnt_kernel<<<(M + 255) / 256, 256>>>(M);
    build_buckets_kernel<<<(E + 255) / 256, 256>>>(ls_rows, ls_cols, ls_vals, E);

    // 2. Tx0 = tile(x)
    tile_x_kernel<<<(M * (F / 4) + 255) / 256, 256>>>(x, tx[0], N);

    // 3. out = feat(Tx0) @ W0 + bias
    gemm_acc_kernel<<<gemm_blocks, 128>>>(tx[0], weight, bias, out, N, 1);

    // 4. Tx1 = L @ Tx0 ; out += feat(Tx1) @ W1
    spmm_cheb_kernel<<<spmm_blocks, 256>>>(tx[0], nullptr, tx[1], M, 1);
    gemm_acc_kernel<<<gemm_blocks, 128>>>(tx[1], weight + (size_t)1 * A_ANG * F * F,
                                          bias, out, N, 0);

    // 5. Chebyshev recurrence
    int ia = 0, ib = 1, ic = 2;
    for (int k = 2; k < K; k++) {
        spmm_cheb_kernel<<<spmm_blocks, 256>>>(tx[ib], tx[ia], tx[ic], M, 0);
        gemm_acc_kernel<<<gemm_blocks, 128>>>(tx[ic], weight + (size_t)k * A_ANG * F * F,
                                              bias, out, N, 0);
        int t = ia; ia = ib; ib = ic; ic = t;
    }
}

// round 8
// speedup vs baseline: 2.5868x; 1.2309x over previous
#include <cuda_runtime.h>
#include <cstring>

// Problem constants (fixed shapes for this problem)
#define A_ANG 8
#define F 64                    // in_size == out_size == 64
#define MAX_N 20000
#define MAX_M (A_ANG * MAX_N)   // 160000
#define CAP 64                  // bucket capacity per row (Poisson(16) -> overflow prob ~1e-12/row)
#define NBUF 4                  // tx ring buffers (4 so spmm_k only clobbers gemm_{k-4}'s input)

// ---------------- scratch (device globals: allocation-free per harness rules) ---------
__device__ int   g_cnt[MAX_M];                          // per-row edge counts
__device__ uint2 g_edges[(size_t)MAX_M * CAP];          // {col, val-bits} buckets, 82MB
__device__ float g_tx[(size_t)NBUF * MAX_M * F];        // four ring feature buffers, 164MB

// ---------------- streams/events (created pre-main; no device memory involved) --------
static cudaStream_t g_sB;
static cudaEvent_t  g_evS[16];   // "tx_k ready" (recorded on stream 0)
static cudaEvent_t  g_evG[16];   // "gemm_k done" (recorded on stream B)
namespace {
struct GInit {
    GInit() {
        cudaStreamCreateWithFlags(&g_sB, cudaStreamNonBlocking);
        for (int i = 0; i < 16; i++) {
            cudaEventCreateWithFlags(&g_evS[i], cudaEventDisableTiming);
            cudaEventCreateWithFlags(&g_evG[i], cudaEventDisableTiming);
        }
    }
};
static GInit g_init;
}

// ---------------- helpers ----------------
__device__ __forceinline__ float2 ffma2(float2 a, float2 b, float2 c) {
    unsigned long long ua, ub, uc, ud;
    memcpy(&ua, &a, 8); memcpy(&ub, &b, 8); memcpy(&uc, &c, 8);
    asm("fma.rn.f32x2 %0, %1, %2, %3;" : "=l"(ud) : "l"(ua), "l"(ub), "l"(uc));
    float2 d; memcpy(&d, &ud, 8);
    return d;
}

// ---------------- kernels ----------------
__global__ void zero_cnt_kernel(int M) {
    int i = blockIdx.x * blockDim.x + threadIdx.x;
    if (i < M) g_cnt[i] = 0;
}

__global__ void build_buckets_kernel(const int* __restrict__ rows,
                                     const int* __restrict__ cols,
                                     const float* __restrict__ vals, int E) {
    int e = blockIdx.x * blockDim.x + threadIdx.x;
    if (e >= E) return;
    int r = rows[e];
    int p = atomicAdd(&g_cnt[r], 1);
    if (p < CAP)
        g_edges[(size_t)r * CAP + p] = make_uint2((unsigned)cols[e], __float_as_uint(vals[e]));
}

// Tx0[a*N + n][:] = x[n][:]
__global__ void tile_x_kernel(const float* __restrict__ x, float* __restrict__ tx0, int N) {
    int idx = blockIdx.x * blockDim.x + threadIdx.x;   // over M * (F/4) float4s
    int total = A_ANG * N * (F / 4);
    if (idx >= total) return;
    int c4 = idx & 15;
    int m  = idx >> 4;
    int n  = m % N;
    ((float4*)tx0)[idx] = __ldg((const float4*)x + n * (F / 4) + c4);
}

// One warp per row. dst = spmm(src)           (first=1)
//                   dst = 2*spmm(src) - prev  (first=0)
// Unroll 8: four uint4 edge loads -> 8 gathers in flight per warp.
__global__ void spmm_cheb_kernel(const float* __restrict__ src,
                                 const float* __restrict__ prev,
                                 float* __restrict__ dst, int M, int first) {
    int w = (int)((blockIdx.x * blockDim.x + threadIdx.x) >> 5);
    if (w >= M) return;
    int lane = threadIdx.x & 31;

    int cnt = g_cnt[w];
    if (cnt > CAP) cnt = CAP;
    const uint2* ep = g_edges + (size_t)w * CAP;

    float ax0 = 0.f, ay0 = 0.f, ax1 = 0.f, ay1 = 0.f;
    float ax2 = 0.f, ay2 = 0.f, ax3 = 0.f, ay3 = 0.f;
    int i = 0;
    for (; i + 7 < cnt; i += 8) {
        uint4 eA = __ldg((const uint4*)(ep + i));
        uint4 eB = __ldg((const uint4*)(ep + i + 2));
        uint4 eC = __ldg((const uint4*)(ep + i + 4));
        uint4 eD = __ldg((const uint4*)(ep + i + 6));
        float2 t0 = __ldg((const float2*)(src + (size_t)eA.x * F) + lane);
        float2 t1 = __ldg((const float2*)(src + (size_t)eA.z * F) + lane);
        float2 t2 = __ldg((const float2*)(src + (size_t)eB.x * F) + lane);
        float2 t3 = __ldg((const float2*)(src + (size_t)eB.z * F) + lane);
        float2 t4 = __ldg((const float2*)(src + (size_t)eC.x * F) + lane);
        float2 t5 = __ldg((const float2*)(src + (size_t)eC.z * F) + lane);
        float2 t6 = __ldg((const float2*)(src + (size_t)eD.x * F) + lane);
        float2 t7 = __ldg((const float2*)(src + (size_t)eD.z * F) + lane);
        float v0 = __uint_as_float(eA.y), v1 = __uint_as_float(eA.w);
        float v2 = __uint_as_float(eB.y), v3 = __uint_as_float(eB.w);
        float v4 = __uint_as_float(eC.y), v5 = __uint_as_float(eC.w);
        float v6 = __uint_as_float(eD.y), v7 = __uint_as_float(eD.w);
        ax0 += v0 * t0.x; ay0 += v0 * t0.y;
        ax1 += v1 * t1.x; ay1 += v1 * t1.y;
        ax2 += v2 * t2.x; ay2 += v2 * t2.y;
        ax3 += v3 * t3.x; ay3 += v3 * t3.y;
        ax0 += v4 * t4.x; ay0 += v4 * t4.y;
        ax1 += v5 * t5.x; ay1 += v5 * t5.y;
        ax2 += v6 * t6.x; ay2 += v6 * t6.y;
        ax3 += v7 * t7.x; ay3 += v7 * t7.y;
    }
    for (; i + 3 < cnt; i += 4) {
        uint4 e01 = __ldg((const uint4*)(ep + i));
        uint4 e23 = __ldg((const uint4*)(ep + i + 2));
        float2 t0 = __ldg((const float2*)(src + (size_t)e01.x * F) + lane);
        float2 t1 = __ldg((const float2*)(src + (size_t)e01.z * F) + lane);
        float2 t2 = __ldg((const float2*)(src + (size_t)e23.x * F) + lane);
        float2 t3 = __ldg((const float2*)(src + (size_t)e23.z * F) + lane);
        float v0 = __uint_as_float(e01.y);
        float v1 = __uint_as_float(e01.w);
        float v2 = __uint_as_float(e23.y);
        float v3 = __uint_as_float(e23.w);
        ax0 += v0 * t0.x; ay0 += v0 * t0.y;
        ax1 += v1 * t1.x; ay1 += v1 * t1.y;
        ax2 += v2 * t2.x; ay2 += v2 * t2.y;
        ax3 += v3 * t3.x; ay3 += v3 * t3.y;
    }
    for (; i < cnt; i++) {
        uint2 e0 = __ldg(&ep[i]);
        float2 t0 = __ldg((const float2*)(src + (size_t)e0.x * F) + lane);
        float v0 = __uint_as_float(e0.y);
        ax0 += v0 * t0.x; ay0 += v0 * t0.y;
    }
    float sx = (ax0 + ax1) + (ax2 + ax3);
    float sy = (ay0 + ay1) + (ay2 + ay3);

    float2 o;
    if (first) {
        o.x = sx; o.y = sy;
    } else {
        float2 p = __ldg((const float2*)(prev + (size_t)w * F) + lane);
        o.x = 2.f * sx - p.x;
        o.y = 2.f * sy - p.y;
    }
    ((float2*)(dst + (size_t)w * F))[lane] = o;
}

// out[n][o] (+)= sum_a sum_i src[a*N+n][i] * Wk[a*64+i][o]   (+ bias if init)
// Block: 128 threads = 4 warps; tile 64 nodes x 64 outs.
// Warp (r,c) owns a 32-node x 32-out quadrant. Lane: ln=l&7 -> 4 nodes, lo=l>>3 -> 8 outs.
// Weight LDS are warp-broadcast; node LDS are conflict-free scalars (pad-65).
// Sv staged with SCALAR stores (pad-65 rows are only 4B-aligned; STS.128 would trap).
__global__ __launch_bounds__(128) void gemm_acc_kernel(const float* __restrict__ src,
                                                       const float* __restrict__ Wk,
                                                       const float* __restrict__ bias,
                                                       float* __restrict__ out,
                                                       int N, int initOut) {
    __shared__ float Sv[64][65];   // [node][j]; pad 65 -> conflict-free scalar column reads
    __shared__ float Sw[64][68];   // [j][out];  pad 68: 272B rows keep 16B align

    int tid = threadIdx.x;
    int lane = tid & 31;
    int w = tid >> 5;            // 0..3
    int r = w & 1;               // node half
    int c = w >> 1;              // out half
    int ln = lane & 7;           // node group of 4 within half
    int lo = lane >> 3;          // out group of 8 within half
    int nodeBase = blockIdx.x * 64;
    int nLoc = 32 * r + 4 * ln;  // local node base (4 nodes)
    int oLoc = 32 * c + 8 * lo;  // local out base (8 outs)

    float2 acc[4][4];
#pragma unroll
    for (int q = 0; q < 4; q++)
#pragma unroll
        for (int i = 0; i < 4; i++) acc[q][i] = make_float2(0.f, 0.f);

    for (int a = 0; a < A_ANG; a++) {
        // stage feature tile (natural layout Sv[node][j]); scalar STS (alignment-safe)
#pragma unroll
        for (int i = tid; i < 64 * 16; i += 128) {
            int rr = i >> 4, c4 = i & 15;
            int n = nodeBase + rr;
            float4 v = make_float4(0.f, 0.f, 0.f, 0.f);
            if (n < N) v = __ldg((const float4*)(src + ((size_t)a * N + n) * F) + c4);
            Sv[rr][c4 * 4 + 0] = v.x;
            Sv[rr][c4 * 4 + 1] = v.y;
            Sv[rr][c4 * 4 + 2] = v.z;
            Sv[rr][c4 * 4 + 3] = v.w;
        }
        // stage weight tile (rows 272B -> 16B aligned, STS.128 OK)
#pragma unroll
        for (int i = tid; i < 64 * 16; i += 128) {
            int rr = i >> 4, c4 = i & 15;
            float4 v = __ldg((const float4*)(Wk + (size_t)(a * F + rr) * F) + c4);
            *(float4*)&Sw[rr][c4 * 4] = v;
        }
        __syncthreads();

#pragma unroll 4
        for (int jj = 0; jj < 64; jj++) {
            float v0 = Sv[nLoc + 0][jj];
            float v1 = Sv[nLoc + 1][jj];
            float v2 = Sv[nLoc + 2][jj];
            float v3 = Sv[nLoc + 3][jj];
            float4 w0 = *(const float4*)&Sw[jj][oLoc];
            float4 w1 = *(const float4*)&Sw[jj][oLoc + 4];
            float2 wp[4] = { make_float2(w0.x, w0.y), make_float2(w0.z, w0.w),
                             make_float2(w1.x, w1.y), make_float2(w1.z, w1.w) };
            float2 vv0 = make_float2(v0, v0);
            float2 vv1 = make_float2(v1, v1);
            float2 vv2 = make_float2(v2, v2);
            float2 vv3 = make_float2(v3, v3);
#pragma unroll
            for (int i = 0; i < 4; i++) {
                acc[0][i] = ffma2(vv0, wp[i], acc[0][i]);
                acc[1][i] = ffma2(vv1, wp[i], acc[1][i]);
                acc[2][i] = ffma2(vv2, wp[i], acc[2][i]);
                acc[3][i] = ffma2(vv3, wp[i], acc[3][i]);
            }
        }
        __syncthreads();
    }

    // epilogue: 4 nodes x 8 outs per thread
#pragma unroll
    for (int q = 0; q < 4; q++) {
        int gn = nodeBase + nLoc + q;
        if (gn >= N) continue;
#pragma unroll
        for (int i = 0; i < 4; i++) {
            int o = oLoc + 2 * i;
            float2* p = (float2*)(out + (size_t)gn * F + o);
            float2 res = acc[q][i];
            if (initOut) {
                float2 b2 = *(const float2*)(bias + o);
                res.x += b2.x; res.y += b2.y;
            } else {
                float2 old = *p;
                res.x += old.x; res.y += old.y;
            }
            *p = res;
        }
    }
}

// ---------------- launch ----------------
// Stream 0 (capture origin): build -> tile -> spmm chain.
// Stream B: gemm chain (gemm_k waits evS[k] = "tx_k ready").
// spmm_k (k>=4) waits evG[k-4] before overwriting gemm_{k-4}'s input ring buffer.
extern "C" void kernel_launch(void* const* d_in, const int* in_sizes, int n_in,
                              void* d_out, int out_size) {
    const float* x       = (const float*)d_in[0];
    const float* ls_vals = (const float*)d_in[1];
    const float* weight  = (const float*)d_in[2];
    const float* bias    = (const float*)d_in[3];
    const int*   ls_rows = (const int*)d_in[4];
    const int*   ls_cols = (const int*)d_in[5];

    int N = in_sizes[0] / F;
    int E = in_sizes[1];
    int M = A_ANG * N;
    int K = in_sizes[2] / (A_ANG * F * F);
    if (K > 16) K = 16;   // event arrays sized 16; problem uses K=8
    float* out = (float*)d_out;

    float* txbuf;
    {
        void* p = nullptr;
        cudaGetSymbolAddress(&p, g_tx);
        txbuf = (float*)p;
    }
    float* tx[NBUF];
    for (int b = 0; b < NBUF; b++) tx[b] = txbuf + (size_t)b * MAX_M * F;

    const int spmm_blocks = (M + 7) / 8;       // 8 warps (rows) per 256-thread block
    const int gemm_blocks = (N + 63) / 64;

    // 1. build per-row edge buckets (one-pass counting "sort")  [stream 0]
    zero_cnt_kernel<<<(M + 255) / 256, 256>>>(M);
    build_buckets_kernel<<<(E + 255) / 256, 256>>>(ls_rows, ls_cols, ls_vals, E);

    // 2. Tx0 = tile(x)  [stream 0]
    tile_x_kernel<<<(M * (F / 4) + 255) / 256, 256>>>(x, tx[0], N);
    cudaEventRecord(g_evS[0], 0);

    // 3. gemm0 on stream B (forks B into the capture)
    cudaStreamWaitEvent(g_sB, g_evS[0], 0);
    gemm_acc_kernel<<<gemm_blocks, 128, 0, g_sB>>>(tx[0], weight, bias, out, N, 1);
    cudaEventRecord(g_evG[0], g_sB);

    // 4. spmm chain on stream 0, gemms on stream B
    for (int k = 1; k < K; k++) {
        if (k >= NBUF) cudaStreamWaitEvent(0, g_evG[k - NBUF], 0);
        if (k == 1)
            spmm_cheb_kernel<<<spmm_blocks, 256>>>(tx[0], nullptr, tx[1 % NBUF], M, 1);
        else
            spmm_cheb_kernel<<<spmm_blocks, 256>>>(tx[(k - 1) % NBUF], tx[(k - 2) % NBUF],
                                                   tx[k % NBUF], M, 0);
        cudaEventRecord(g_evS[k], 0);

        cudaStreamWaitEvent(g_sB, g_evS[k], 0);
        gemm_acc_kernel<<<gemm_blocks, 128, 0, g_sB>>>(tx[k % NBUF],
                                                       weight + (size_t)k * A_ANG * F * F,
                                                       bias, out, N, 0);
        cudaEventRecord(g_evG[k], g_sB);
    }

    // 5. join stream B back into the capture origin
    cudaStreamWaitEvent(0, g_evG[K - 1], 0);
}

// round 9
// speedup vs baseline: 2.7211x; 1.0519x over previous
#include <cuda_runtime.h>
#include <cstring>

// Problem constants (fixed shapes for this problem)
#define A_ANG 8
#define F 64                    // in_size == out_size == 64
#define MAX_N 20000
#define MAX_M (A_ANG * MAX_N)   // 160000
#define CAP 64                  // bucket capacity per row (Poisson(16) -> overflow prob ~1e-12/row)
#define NBUF 4                  // tx ring buffers (4 so spmm_k only clobbers gemm_{k-4}'s input)

// ---------------- scratch (device globals: allocation-free per harness rules) ---------
__device__ int   g_cnt[MAX_M];                          // per-row edge counts
__device__ uint2 g_edges[(size_t)MAX_M * CAP];          // {col, val-bits} buckets, 82MB
__device__ float g_tx[(size_t)NBUF * MAX_M * F];        // four ring feature buffers, 164MB

// ---------------- streams/events (created pre-main; no device memory involved) --------
static cudaStream_t g_sB;
static cudaEvent_t  g_evS[16];   // "tx_k ready" (recorded on stream 0)
static cudaEvent_t  g_evG[16];   // "gemm_k done" (recorded on stream B)
namespace {
struct GInit {
    GInit() {
        cudaStreamCreateWithFlags(&g_sB, cudaStreamNonBlocking);
        for (int i = 0; i < 16; i++) {
            cudaEventCreateWithFlags(&g_evS[i], cudaEventDisableTiming);
            cudaEventCreateWithFlags(&g_evG[i], cudaEventDisableTiming);
        }
    }
};
static GInit g_init;
}

// ---------------- helpers ----------------
__device__ __forceinline__ float2 ffma2(float2 a, float2 b, float2 c) {
    unsigned long long ua, ub, uc, ud;
    memcpy(&ua, &a, 8); memcpy(&ub, &b, 8); memcpy(&uc, &c, 8);
    asm("fma.rn.f32x2 %0, %1, %2, %3;" : "=l"(ud) : "l"(ua), "l"(ub), "l"(uc));
    float2 d; memcpy(&d, &ud, 8);
    return d;
}

// ---------------- kernels ----------------
__global__ void zero_cnt_kernel(int M) {
    int i = blockIdx.x * blockDim.x + threadIdx.x;
    if (i < M) g_cnt[i] = 0;
}

__global__ void build_buckets_kernel(const int* __restrict__ rows,
                                     const int* __restrict__ cols,
                                     const float* __restrict__ vals, int E) {
    int e = blockIdx.x * blockDim.x + threadIdx.x;
    if (e >= E) return;
    int r = rows[e];
    int p = atomicAdd(&g_cnt[r], 1);
    if (p < CAP)
        g_edges[(size_t)r * CAP + p] = make_uint2((unsigned)cols[e], __float_as_uint(vals[e]));
}

// Tx0[a*N + n][:] = x[n][:]
__global__ void tile_x_kernel(const float* __restrict__ x, float* __restrict__ tx0, int N) {
    int idx = blockIdx.x * blockDim.x + threadIdx.x;   // over M * (F/4) float4s
    int total = A_ANG * N * (F / 4);
    if (idx >= total) return;
    int c4 = idx & 15;
    int m  = idx >> 4;
    int n  = m % N;
    ((float4*)tx0)[idx] = __ldg((const float4*)x + n * (F / 4) + c4);
}

// One warp per row. dst = spmm(src)           (first=1)
//                   dst = 2*spmm(src) - prev  (first=0)
// Streams (edges, prev, dst) use .cs hints so only the gathered src stays L2-resident
// (src 41MB fits in the 126MB L2; the full naive footprint ~143MB does not).
__global__ void spmm_cheb_kernel(const float* __restrict__ src,
                                 const float* __restrict__ prev,
                                 float* __restrict__ dst, int M, int first) {
    int w = (int)((blockIdx.x * blockDim.x + threadIdx.x) >> 5);
    if (w >= M) return;
    int lane = threadIdx.x & 31;

    int cnt = g_cnt[w];
    if (cnt > CAP) cnt = CAP;
    const uint2* ep = g_edges + (size_t)w * CAP;

    float ax0 = 0.f, ay0 = 0.f, ax1 = 0.f, ay1 = 0.f;
    float ax2 = 0.f, ay2 = 0.f, ax3 = 0.f, ay3 = 0.f;
    int i = 0;
    for (; i + 7 < cnt; i += 8) {
        uint4 eA = __ldcs((const uint4*)(ep + i));
        uint4 eB = __ldcs((const uint4*)(ep + i + 2));
        uint4 eC = __ldcs((const uint4*)(ep + i + 4));
        uint4 eD = __ldcs((const uint4*)(ep + i + 6));
        float2 t0 = __ldg((const float2*)(src + (size_t)eA.x * F) + lane);
        float2 t1 = __ldg((const float2*)(src + (size_t)eA.z * F) + lane);
        float2 t2 = __ldg((const float2*)(src + (size_t)eB.x * F) + lane);
        float2 t3 = __ldg((const float2*)(src + (size_t)eB.z * F) + lane);
        float2 t4 = __ldg((const float2*)(src + (size_t)eC.x * F) + lane);
        float2 t5 = __ldg((const float2*)(src + (size_t)eC.z * F) + lane);
        float2 t6 = __ldg((const float2*)(src + (size_t)eD.x * F) + lane);
        float2 t7 = __ldg((const float2*)(src + (size_t)eD.z * F) + lane);
        float v0 = __uint_as_float(eA.y), v1 = __uint_as_float(eA.w);
        float v2 = __uint_as_float(eB.y), v3 = __uint_as_float(eB.w);
        float v4 = __uint_as_float(eC.y), v5 = __uint_as_float(eC.w);
        float v6 = __uint_as_float(eD.y), v7 = __uint_as_float(eD.w);
        ax0 += v0 * t0.x; ay0 += v0 * t0.y;
        ax1 += v1 * t1.x; ay1 += v1 * t1.y;
        ax2 += v2 * t2.x; ay2 += v2 * t2.y;
        ax3 += v3 * t3.x; ay3 += v3 * t3.y;
        ax0 += v4 * t4.x; ay0 += v4 * t4.y;
        ax1 += v5 * t5.x; ay1 += v5 * t5.y;
        ax2 += v6 * t6.x; ay2 += v6 * t6.y;
        ax3 += v7 * t7.x; ay3 += v7 * t7.y;
    }
    for (; i + 3 < cnt; i += 4) {
        uint4 e01 = __ldcs((const uint4*)(ep + i));
        uint4 e23 = __ldcs((const uint4*)(ep + i + 2));
        float2 t0 = __ldg((const float2*)(src + (size_t)e01.x * F) + lane);
        float2 t1 = __ldg((const float2*)(src + (size_t)e01.z * F) + lane);
        float2 t2 = __ldg((const float2*)(src + (size_t)e23.x * F) + lane);
        float2 t3 = __ldg((const float2*)(src + (size_t)e23.z * F) + lane);
        float v0 = __uint_as_float(e01.y);
        float v1 = __uint_as_float(e01.w);
        float v2 = __uint_as_float(e23.y);
        float v3 = __uint_as_float(e23.w);
        ax0 += v0 * t0.x; ay0 += v0 * t0.y;
        ax1 += v1 * t1.x; ay1 += v1 * t1.y;
        ax2 += v2 * t2.x; ay2 += v2 * t2.y;
        ax3 += v3 * t3.x; ay3 += v3 * t3.y;
    }
    for (; i < cnt; i++) {
        uint2 e0 = __ldcs(&ep[i]);
        float2 t0 = __ldg((const float2*)(src + (size_t)e0.x * F) + lane);
        float v0 = __uint_as_float(e0.y);
        ax0 += v0 * t0.x; ay0 += v0 * t0.y;
    }
    float sx = (ax0 + ax1) + (ax2 + ax3);
    float sy = (ay0 + ay1) + (ay2 + ay3);

    float2 o;
    if (first) {
        o.x = sx; o.y = sy;
    } else {
        float2 p = __ldcs((const float2*)(prev + (size_t)w * F) + lane);
        o.x = 2.f * sx - p.x;
        o.y = 2.f * sy - p.y;
    }
    __stcs((float2*)(dst + (size_t)w * F) + lane, o);
}

// out[n][o] (+)= sum_a sum_i src[a*N+n][i] * Wk[a*64+i][o]   (+ bias if init)
// Block: 128 threads = 4 warps; tile 64 nodes x 64 outs.
// Warp (r,c) owns a 32-node x 32-out quadrant. Lane: ln=l&7 -> 4 nodes, lo=l>>3 -> 8 outs.
// Weight LDS are warp-broadcast; node LDS are conflict-free scalars (pad-65).
// Sv staged with SCALAR stores (pad-65 rows are only 4B-aligned; STS.128 would trap).
__global__ __launch_bounds__(128) void gemm_acc_kernel(const float* __restrict__ src,
                                                       const float* __restrict__ Wk,
                                                       const float* __restrict__ bias,
                                                       float* __restrict__ out,
                                                       int N, int initOut) {
    __shared__ float Sv[64][65];   // [node][j]; pad 65 -> conflict-free scalar column reads
    __shared__ float Sw[64][68];   // [j][out];  pad 68: 272B rows keep 16B align

    int tid = threadIdx.x;
    int lane = tid & 31;
    int w = tid >> 5;            // 0..3
    int r = w & 1;               // node half
    int c = w >> 1;              // out half
    int ln = lane & 7;           // node group of 4 within half
    int lo = lane >> 3;          // out group of 8 within half
    int nodeBase = blockIdx.x * 64;
    int nLoc = 32 * r + 4 * ln;  // local node base (4 nodes)
    int oLoc = 32 * c + 8 * lo;  // local out base (8 outs)

    float2 acc[4][4];
#pragma unroll
    for (int q = 0; q < 4; q++)
#pragma unroll
        for (int i = 0; i < 4; i++) acc[q][i] = make_float2(0.f, 0.f);

    for (int a = 0; a < A_ANG; a++) {
        // stage feature tile (natural layout Sv[node][j]); scalar STS (alignment-safe)
#pragma unroll
        for (int i = tid; i < 64 * 16; i += 128) {
            int rr = i >> 4, c4 = i & 15;
            int n = nodeBase + rr;
            float4 v = make_float4(0.f, 0.f, 0.f, 0.f);
            if (n < N) v = __ldg((const float4*)(src + ((size_t)a * N + n) * F) + c4);
            Sv[rr][c4 * 4 + 0] = v.x;
            Sv[rr][c4 * 4 + 1] = v.y;
            Sv[rr][c4 * 4 + 2] = v.z;
            Sv[rr][c4 * 4 + 3] = v.w;
        }
        // stage weight tile (rows 272B -> 16B aligned, STS.128 OK)
#pragma unroll
        for (int i = tid; i < 64 * 16; i += 128) {
            int rr = i >> 4, c4 = i & 15;
            float4 v = __ldg((const float4*)(Wk + (size_t)(a * F + rr) * F) + c4);
            *(float4*)&Sw[rr][c4 * 4] = v;
        }
        __syncthreads();

#pragma unroll 4
        for (int jj = 0; jj < 64; jj++) {
            float v0 = Sv[nLoc + 0][jj];
            float v1 = Sv[nLoc + 1][jj];
            float v2 = Sv[nLoc + 2][jj];
            float v3 = Sv[nLoc + 3][jj];
            float4 w0 = *(const float4*)&Sw[jj][oLoc];
            float4 w1 = *(const float4*)&Sw[jj][oLoc + 4];
            float2 wp[4] = { make_float2(w0.x, w0.y), make_float2(w0.z, w0.w),
                             make_float2(w1.x, w1.y), make_float2(w1.z, w1.w) };
            float2 vv0 = make_float2(v0, v0);
            float2 vv1 = make_float2(v1, v1);
            float2 vv2 = make_float2(v2, v2);
            float2 vv3 = make_float2(v3, v3);
#pragma unroll
            for (int i = 0; i < 4; i++) {
                acc[0][i] = ffma2(vv0, wp[i], acc[0][i]);
                acc[1][i] = ffma2(vv1, wp[i], acc[1][i]);
                acc[2][i] = ffma2(vv2, wp[i], acc[2][i]);
                acc[3][i] = ffma2(vv3, wp[i], acc[3][i]);
            }
        }
        __syncthreads();
    }

    // epilogue: 4 nodes x 8 outs per thread
#pragma unroll
    for (int q = 0; q < 4; q++) {
        int gn = nodeBase + nLoc + q;
        if (gn >= N) continue;
#pragma unroll
        for (int i = 0; i < 4; i++) {
            int o = oLoc + 2 * i;
            float2* p = (float2*)(out + (size_t)gn * F + o);
            float2 res = acc[q][i];
            if (initOut) {
                float2 b2 = *(const float2*)(bias + o);
                res.x += b2.x; res.y += b2.y;
            } else {
                float2 old = *p;
                res.x += old.x; res.y += old.y;
            }
            *p = res;
        }
    }
}

// ---------------- launch ----------------
// Stream 0 (capture origin): build -> tile -> spmm chain.
// Stream B: gemm chain (gemm_k waits evS[k] = "tx_k ready").
// spmm_k (k>=4) waits evG[k-4] before overwriting gemm_{k-4}'s input ring buffer.
extern "C" void kernel_launch(void* const* d_in, const int* in_sizes, int n_in,
                              void* d_out, int out_size) {
    const float* x       = (const float*)d_in[0];
    const float* ls_vals = (const float*)d_in[1];
    const float* weight  = (const float*)d_in[2];
    const float* bias    = (const float*)d_in[3];
    const int*   ls_rows = (const int*)d_in[4];
    const int*   ls_cols = (const int*)d_in[5];

    int N = in_sizes[0] / F;
    int E = in_sizes[1];
    int M = A_ANG * N;
    int K = in_sizes[2] / (A_ANG * F * F);
    if (K > 16) K = 16;   // event arrays sized 16; problem uses K=8
    float* out = (float*)d_out;

    float* txbuf;
    {
        void* p = nullptr;
        cudaGetSymbolAddress(&p, g_tx);
        txbuf = (float*)p;
    }
    float* tx[NBUF];
    for (int b = 0; b < NBUF; b++) tx[b] = txbuf + (size_t)b * MAX_M * F;

    const int spmm_blocks = (M + 7) / 8;       // 8 warps (rows) per 256-thread block
    const int gemm_blocks = (N + 63) / 64;

    // 1. build per-row edge buckets (one-pass counting "sort")  [stream 0]
    zero_cnt_kernel<<<(M + 255) / 256, 256>>>(M);
    build_buckets_kernel<<<(E + 255) / 256, 256>>>(ls_rows, ls_cols, ls_vals, E);

    // 2. Tx0 = tile(x)  [stream 0]
    tile_x_kernel<<<(M * (F / 4) + 255) / 256, 256>>>(x, tx[0], N);
    cudaEventRecord(g_evS[0], 0);

    // 3. gemm0 on stream B (forks B into the capture)
    cudaStreamWaitEvent(g_sB, g_evS[0], 0);
    gemm_acc_kernel<<<gemm_blocks, 128, 0, g_sB>>>(tx[0], weight, bias, out, N, 1);
    cudaEventRecord(g_evG[0], g_sB);

    // 4. spmm chain on stream 0, gemms on stream B
    for (int k = 1; k < K; k++) {
        if (k >= NBUF) cudaStreamWaitEvent(0, g_evG[k - NBUF], 0);
        if (k == 1)
            spmm_cheb_kernel<<<spmm_blocks, 256>>>(tx[0], nullptr, tx[1 % NBUF], M, 1);
        else
            spmm_cheb_kernel<<<spmm_blocks, 256>>>(tx[(k - 1) % NBUF], tx[(k - 2) % NBUF],
                                                   tx[k % NBUF], M, 0);
        cudaEventRecord(g_evS[k], 0);

        cudaStreamWaitEvent(g_sB, g_evS[k], 0);
        gemm_acc_kernel<<<gemm_blocks, 128, 0, g_sB>>>(tx[k % NBUF],
                                                       weight + (size_t)k * A_ANG * F * F,
                                                       bias, out, N, 0);
        cudaEventRecord(g_evG[k], g_sB);
    }

    // 5. join stream B back into the capture origin
    cudaStreamWaitEvent(0, g_evG[K - 1], 0);
}